// round 13
// baseline (speedup 1.0000x reference)
#include <cuda_runtime.h>
#include <cstdint>

// out[b,v,h,w] = sum_c R[h,v,c] * feats[b,c,h,w]
// Block-sparse RoPE: 2x2 rotation per channel pair, coefficients read from
// the dense R input so arithmetic matches the reference exactly.
//
// R12: persistent grid-stride variant. All correctly-coalesced kernels pin
// at ~6.45 TB/s = the sm_103a LTS cap (~6300 B/cyc, path-independent); the
// only un-attacked term in the T_chip model is the wave/tail/spread cost of
// 16384 tiny CTAs. Here: 1184 CTAs (148 SMs x 8), each thread loops over
// chunks with a 2x-unrolled body (v8 loads, MLP=4 front-batched per iter),
// zero wave transitions. v8 (256-bit) accesses + evict_last on feats
// batches 0..5 carried over from R11.

#define B_DIM 16
#define C_DIM 256
#define HW 16384u                   // H*W floats per (b,c) plane
#define PERSIST_ELEMS (6u * C_DIM * HW)   // feats batches 0..5 -> evict_last
#define NCHUNK (16u * 128u * 2048u)       // (b, pair, idx8) work items
#define CTAS 1184u                  // 148 SMs * 8 resident CTAs
#define THREADS 256u

struct f8 { float v[8]; };

__device__ __forceinline__ f8 ld8_keep(const float* p) {
    f8 r;
    asm("ld.global.nc.L2::evict_last.v8.f32 {%0,%1,%2,%3,%4,%5,%6,%7}, [%8];"
        : "=f"(r.v[0]), "=f"(r.v[1]), "=f"(r.v[2]), "=f"(r.v[3]),
          "=f"(r.v[4]), "=f"(r.v[5]), "=f"(r.v[6]), "=f"(r.v[7])
        : "l"(p));
    return r;
}
__device__ __forceinline__ f8 ld8(const float* p) {
    f8 r;
    asm("ld.global.nc.v8.f32 {%0,%1,%2,%3,%4,%5,%6,%7}, [%8];"
        : "=f"(r.v[0]), "=f"(r.v[1]), "=f"(r.v[2]), "=f"(r.v[3]),
          "=f"(r.v[4]), "=f"(r.v[5]), "=f"(r.v[6]), "=f"(r.v[7])
        : "l"(p));
    return r;
}
__device__ __forceinline__ void st8_cs(float* p, const f8& r) {
    asm volatile("st.global.cs.v8.f32 [%0], {%1,%2,%3,%4,%5,%6,%7,%8};"
                 :: "l"(p),
                    "f"(r.v[0]), "f"(r.v[1]), "f"(r.v[2]), "f"(r.v[3]),
                    "f"(r.v[4]), "f"(r.v[5]), "f"(r.v[6]), "f"(r.v[7])
                 : "memory");
}

__device__ __forceinline__ void do_chunk(const float* __restrict__ feats,
                                         const float* __restrict__ R,
                                         float* __restrict__ out,
                                         unsigned int t)
{
    unsigned int idx8 = t & 2047u;        // 32B chunk within the 64KB plane
    unsigned int cp   = (t >> 11) & 127u; // channel pair
    unsigned int b    = t >> 18;          // batch 0..15
    unsigned int v = cp << 1;
    unsigned int h = idx8 >> 4;           // 16 chunks per W=128 row

    unsigned int base = (b * C_DIM + v) * HW + (idx8 << 3);

    f8 xe, xo;
    if (base < PERSIST_ELEMS) {
        xe = ld8_keep(feats + base);
        xo = ld8_keep(feats + base + HW);
    } else {
        xe = ld8(feats + base);
        xo = ld8(feats + base + HW);
    }

    const float* __restrict__ Rblk =
        R + (size_t)h * (C_DIM * C_DIM) + (size_t)v * C_DIM + v;
    float c00 = __ldg(Rblk + 0);
    float c01 = __ldg(Rblk + 1);
    float c10 = __ldg(Rblk + C_DIM);
    float c11 = __ldg(Rblk + C_DIM + 1);

    f8 ye, yo;
#pragma unroll
    for (int i = 0; i < 8; i++) {
        ye.v[i] = fmaf(c00, xe.v[i], c01 * xo.v[i]);
        yo.v[i] = fmaf(c10, xe.v[i], c11 * xo.v[i]);
    }
    st8_cs(out + base,      ye);
    st8_cs(out + base + HW, yo);
}

__global__ void __launch_bounds__(THREADS, 8)
rope_pair_kernel(const float* __restrict__ feats,
                 const float* __restrict__ R,
                 float* __restrict__ out)
{
    const unsigned int stride = CTAS * THREADS;            // 303,104
    unsigned int t = blockIdx.x * THREADS + threadIdx.x;

    // NCHUNK = 4,194,304 = 13 * stride + 253,952 : 13 full strides + tail.
    // 2x unrolled steady-state loop (ptxas front-batches the 4 loads).
#pragma unroll 1
    for (; t + stride < NCHUNK; t += 2u * stride) {
        do_chunk(feats, R, out, t);
        do_chunk(feats, R, out, t + stride);
    }
    if (t < NCHUNK)
        do_chunk(feats, R, out, t);
}

extern "C" void kernel_launch(void* const* d_in, const int* in_sizes, int n_in,
                              void* d_out, int out_size)
{
    const float* feats = (const float*)d_in[0];
    const float* R     = (const float*)d_in[1];
    if (n_in >= 2 && in_sizes[0] < in_sizes[1]) {  // feats is the bigger input
        const float* tmp = feats; feats = R; R = tmp;
    }
    float* out = (float*)d_out;

    rope_pair_kernel<<<CTAS, THREADS>>>(feats, R, out);
}

// round 14
// speedup vs baseline: 1.0010x; 1.0010x over previous
#include <cuda_runtime.h>
#include <cstdint>

// out[b,v,h,w] = sum_c R[h,v,c] * feats[b,c,h,w]
// Block-sparse RoPE: 2x2 rotation per channel pair, coefficients read from
// the dense R input so arithmetic matches the reference exactly.
//
// R12: persistent grid-stride variant. All correctly-coalesced kernels pin
// at ~6.45 TB/s = the sm_103a LTS cap (~6300 B/cyc, path-independent); the
// only un-attacked term in the T_chip model is the wave/tail/spread cost of
// 16384 tiny CTAs. Here: 1184 CTAs (148 SMs x 8), each thread loops over
// chunks with a 2x-unrolled body (v8 loads, MLP=4 front-batched per iter),
// zero wave transitions. v8 (256-bit) accesses + evict_last on feats
// batches 0..5 carried over from R11.

#define B_DIM 16
#define C_DIM 256
#define HW 16384u                   // H*W floats per (b,c) plane
#define PERSIST_ELEMS (6u * C_DIM * HW)   // feats batches 0..5 -> evict_last
#define NCHUNK (16u * 128u * 2048u)       // (b, pair, idx8) work items
#define CTAS 1184u                  // 148 SMs * 8 resident CTAs
#define THREADS 256u

struct f8 { float v[8]; };

__device__ __forceinline__ f8 ld8_keep(const float* p) {
    f8 r;
    asm("ld.global.nc.L2::evict_last.v8.f32 {%0,%1,%2,%3,%4,%5,%6,%7}, [%8];"
        : "=f"(r.v[0]), "=f"(r.v[1]), "=f"(r.v[2]), "=f"(r.v[3]),
          "=f"(r.v[4]), "=f"(r.v[5]), "=f"(r.v[6]), "=f"(r.v[7])
        : "l"(p));
    return r;
}
__device__ __forceinline__ f8 ld8(const float* p) {
    f8 r;
    asm("ld.global.nc.v8.f32 {%0,%1,%2,%3,%4,%5,%6,%7}, [%8];"
        : "=f"(r.v[0]), "=f"(r.v[1]), "=f"(r.v[2]), "=f"(r.v[3]),
          "=f"(r.v[4]), "=f"(r.v[5]), "=f"(r.v[6]), "=f"(r.v[7])
        : "l"(p));
    return r;
}
__device__ __forceinline__ void st8_cs(float* p, const f8& r) {
    asm volatile("st.global.cs.v8.f32 [%0], {%1,%2,%3,%4,%5,%6,%7,%8};"
                 :: "l"(p),
                    "f"(r.v[0]), "f"(r.v[1]), "f"(r.v[2]), "f"(r.v[3]),
                    "f"(r.v[4]), "f"(r.v[5]), "f"(r.v[6]), "f"(r.v[7])
                 : "memory");
}

__device__ __forceinline__ void do_chunk(const float* __restrict__ feats,
                                         const float* __restrict__ R,
                                         float* __restrict__ out,
                                         unsigned int t)
{
    unsigned int idx8 = t & 2047u;        // 32B chunk within the 64KB plane
    unsigned int cp   = (t >> 11) & 127u; // channel pair
    unsigned int b    = t >> 18;          // batch 0..15
    unsigned int v = cp << 1;
    unsigned int h = idx8 >> 4;           // 16 chunks per W=128 row

    unsigned int base = (b * C_DIM + v) * HW + (idx8 << 3);

    f8 xe, xo;
    if (base < PERSIST_ELEMS) {
        xe = ld8_keep(feats + base);
        xo = ld8_keep(feats + base + HW);
    } else {
        xe = ld8(feats + base);
        xo = ld8(feats + base + HW);
    }

    const float* __restrict__ Rblk =
        R + (size_t)h * (C_DIM * C_DIM) + (size_t)v * C_DIM + v;
    float c00 = __ldg(Rblk + 0);
    float c01 = __ldg(Rblk + 1);
    float c10 = __ldg(Rblk + C_DIM);
    float c11 = __ldg(Rblk + C_DIM + 1);

    f8 ye, yo;
#pragma unroll
    for (int i = 0; i < 8; i++) {
        ye.v[i] = fmaf(c00, xe.v[i], c01 * xo.v[i]);
        yo.v[i] = fmaf(c10, xe.v[i], c11 * xo.v[i]);
    }
    st8_cs(out + base,      ye);
    st8_cs(out + base + HW, yo);
}

__global__ void __launch_bounds__(THREADS, 8)
rope_pair_kernel(const float* __restrict__ feats,
                 const float* __restrict__ R,
                 float* __restrict__ out)
{
    const unsigned int stride = CTAS * THREADS;            // 303,104
    unsigned int t = blockIdx.x * THREADS + threadIdx.x;

    // NCHUNK = 4,194,304 = 13 * stride + 253,952 : 13 full strides + tail.
    // 2x unrolled steady-state loop (ptxas front-batches the 4 loads).
#pragma unroll 1
    for (; t + stride < NCHUNK; t += 2u * stride) {
        do_chunk(feats, R, out, t);
        do_chunk(feats, R, out, t + stride);
    }
    if (t < NCHUNK)
        do_chunk(feats, R, out, t);
}

extern "C" void kernel_launch(void* const* d_in, const int* in_sizes, int n_in,
                              void* d_out, int out_size)
{
    const float* feats = (const float*)d_in[0];
    const float* R     = (const float*)d_in[1];
    if (n_in >= 2 && in_sizes[0] < in_sizes[1]) {  // feats is the bigger input
        const float* tmp = feats; feats = R; R = tmp;
    }
    float* out = (float*)d_out;

    rope_pair_kernel<<<CTAS, THREADS>>>(feats, R, out);
}

// round 15
// speedup vs baseline: 1.1435x; 1.1424x over previous
#include <cuda_runtime.h>
#include <cstdint>

// out[b,v,h,w] = sum_c R[h,v,c] * feats[b,c,h,w]
// Block-sparse RoPE: 2x2 rotation per channel pair, coefficients read from
// the dense R input so arithmetic matches the reference exactly.
//
// R14: merge of the two proven-good one-shot designs.
//  - R7 batch pairing: thread handles (b, pair, chunk) AND (b+8, ...) ->
//    4 independent front-batched loads (MLP_p1=4), shared R coefficients.
//  - R11 256-bit accesses: v8.f32 LDG.256/STG.256, lane i at 32B*i ->
//    1024B fully-contiguous warp footprint per instruction.
//  - One-shot grid (8192 CTAs): the CTA launch pipeline provides cross-tile
//    MLP for free (R12/R13 post-mortem: persistent loops serialize on the
//    store->load ordering and regress 14%).
//  - Stores: st.global.cs WITHOUT a "memory" clobber (disjoint addresses;
//    lets ptxas schedule freely). evict_last on feats batches 0..5 (free).

#define B_DIM 16
#define C_DIM 256
#define HW 16384u                       // H*W floats per (b,c) plane
#define BSTRIDE (8u * C_DIM * HW)       // 8 batches of feats/out
#define PERSIST_B 6u                    // feats batches 0..5 -> evict_last

struct f8 { float v[8]; };

__device__ __forceinline__ f8 ld8_keep(const float* p) {
    f8 r;
    asm("ld.global.nc.L2::evict_last.v8.f32 {%0,%1,%2,%3,%4,%5,%6,%7}, [%8];"
        : "=f"(r.v[0]), "=f"(r.v[1]), "=f"(r.v[2]), "=f"(r.v[3]),
          "=f"(r.v[4]), "=f"(r.v[5]), "=f"(r.v[6]), "=f"(r.v[7])
        : "l"(p));
    return r;
}
__device__ __forceinline__ f8 ld8(const float* p) {
    f8 r;
    asm("ld.global.nc.v8.f32 {%0,%1,%2,%3,%4,%5,%6,%7}, [%8];"
        : "=f"(r.v[0]), "=f"(r.v[1]), "=f"(r.v[2]), "=f"(r.v[3]),
          "=f"(r.v[4]), "=f"(r.v[5]), "=f"(r.v[6]), "=f"(r.v[7])
        : "l"(p));
    return r;
}
__device__ __forceinline__ void st8_cs(float* p, const f8& r) {
    // volatile (must not be deleted) but NO memory clobber: all stores in
    // this kernel hit disjoint addresses, let ptxas interleave freely.
    asm volatile("st.global.cs.v8.f32 [%0], {%1,%2,%3,%4,%5,%6,%7,%8};"
                 :: "l"(p),
                    "f"(r.v[0]), "f"(r.v[1]), "f"(r.v[2]), "f"(r.v[3]),
                    "f"(r.v[4]), "f"(r.v[5]), "f"(r.v[6]), "f"(r.v[7]));
}

__global__ void __launch_bounds__(256, 4)
rope_pair_kernel(const float* __restrict__ feats,
                 const float* __restrict__ R,
                 float* __restrict__ out)
{
    // Thread id over (b<8, pair, idx8): 8 * 128 * 2048 = 2,097,152
    unsigned int t = blockIdx.x * 256u + threadIdx.x;

    unsigned int idx8 = t & 2047u;        // 32B chunk within the 64KB plane
    unsigned int cp   = (t >> 11) & 127u; // channel pair
    unsigned int b    = t >> 18;          // batch 0..7 (also handles b+8)

    unsigned int v = cp << 1;             // even channel index
    unsigned int h = idx8 >> 4;           // 16 chunks per W=128 row

    unsigned int base = (b * C_DIM + v) * HW + (idx8 << 3);

    // Four independent 32B/lane loads, front-batched (MLP_p1 = 4).
    f8 xe0, xo0;
    if (b < PERSIST_B) {
        xe0 = ld8_keep(feats + base);
        xo0 = ld8_keep(feats + base + HW);
    } else {
        xe0 = ld8(feats + base);
        xo0 = ld8(feats + base + HW);
    }
    f8 xe1 = ld8(feats + base + BSTRIDE);
    f8 xo1 = ld8(feats + base + BSTRIDE + HW);

    // 2x2 rotation block: warp-uniform per h (2 distinct h per warp),
    // cached path — reused by all 16 batches.
    const float* __restrict__ Rblk =
        R + (size_t)h * (C_DIM * C_DIM) + (size_t)v * C_DIM + v;
    float c00 = __ldg(Rblk + 0);
    float c01 = __ldg(Rblk + 1);
    float c10 = __ldg(Rblk + C_DIM);
    float c11 = __ldg(Rblk + C_DIM + 1);

    f8 ye, yo;
#pragma unroll
    for (int i = 0; i < 8; i++) {
        ye.v[i] = fmaf(c00, xe0.v[i], c01 * xo0.v[i]);
        yo.v[i] = fmaf(c10, xe0.v[i], c11 * xo0.v[i]);
    }
    st8_cs(out + base,      ye);
    st8_cs(out + base + HW, yo);

#pragma unroll
    for (int i = 0; i < 8; i++) {
        ye.v[i] = fmaf(c00, xe1.v[i], c01 * xo1.v[i]);
        yo.v[i] = fmaf(c10, xe1.v[i], c11 * xo1.v[i]);
    }
    st8_cs(out + base + BSTRIDE,      ye);
    st8_cs(out + base + BSTRIDE + HW, yo);
}

extern "C" void kernel_launch(void* const* d_in, const int* in_sizes, int n_in,
                              void* d_out, int out_size)
{
    const float* feats = (const float*)d_in[0];
    const float* R     = (const float*)d_in[1];
    if (n_in >= 2 && in_sizes[0] < in_sizes[1]) {  // feats is the bigger input
        const float* tmp = feats; feats = R; R = tmp;
    }
    float* out = (float*)d_out;

    // 2,097,152 threads / 256 = 8,192 blocks
    const unsigned int total_threads =
        (unsigned int)(B_DIM / 2) * (C_DIM / 2) * (HW / 8);
    rope_pair_kernel<<<total_threads / 256u, 256u>>>(feats, R, out);
}

// round 16
// speedup vs baseline: 1.1466x; 1.0027x over previous
#include <cuda_runtime.h>
#include <cstdint>

// out[b,v,h,w] = sum_c R[h,v,c] * feats[b,c,h,w]
// Block-sparse RoPE: each 2x2 channel-pair block of R is
//   [ c00 c01 ]  applied to  [ x_even ]
//   [ c10 c11 ]              [ x_odd  ]
// Coefficients are read from the dense R input, so the arithmetic matches
// the reference einsum exactly (rel_err ~4e-8).
//
// FINAL (R15): this problem is HBM/LTS mixed-stream bound. 512MB compulsory
// traffic (feats read once + out written once) at the measured ~6.45 TB/s
// read+write ceiling = ~76.5us kernel floor; all correctly-coalesced
// variants (v4/v8, MLP 2/4, cache hints, persistence) land within 3% of it.
// Bounded levers: L2 residency across replays (evict_last loses to 416MB/
// replay churn), persistent grid (store-ordering serializes inter-tile MLP,
// -14%), 256-bit accesses and deeper MLP (bytes/cyc invariant).
//
// Configuration = best measured: one-shot grid, 256-bit v8 accesses (lane i
// at 32B*i -> 1024B fully-contiguous warp footprint per instruction),
// 2 loads + 2 stores per thread, .cs streaming stores, R on the cached path
// (64KB, L2-hot, warp-uniform loads).

#define C_DIM 256
#define HW 16384u                   // H*W floats per (b,c) plane

struct f8 { float v[8]; };

__device__ __forceinline__ f8 ld8(const float* p) {
    f8 r;
    asm("ld.global.nc.v8.f32 {%0,%1,%2,%3,%4,%5,%6,%7}, [%8];"
        : "=f"(r.v[0]), "=f"(r.v[1]), "=f"(r.v[2]), "=f"(r.v[3]),
          "=f"(r.v[4]), "=f"(r.v[5]), "=f"(r.v[6]), "=f"(r.v[7])
        : "l"(p));
    return r;
}
__device__ __forceinline__ void st8_cs(float* p, const f8& r) {
    asm volatile("st.global.cs.v8.f32 [%0], {%1,%2,%3,%4,%5,%6,%7,%8};"
                 :: "l"(p),
                    "f"(r.v[0]), "f"(r.v[1]), "f"(r.v[2]), "f"(r.v[3]),
                    "f"(r.v[4]), "f"(r.v[5]), "f"(r.v[6]), "f"(r.v[7]));
}

__global__ void __launch_bounds__(256, 8)
rope_pair_kernel(const float* __restrict__ feats,
                 const float* __restrict__ R,
                 float* __restrict__ out)
{
    // Thread id over (b, pair, idx8): 16 * 128 * 2048 = 4,194,304
    unsigned int t = blockIdx.x * 256u + threadIdx.x;

    unsigned int idx8 = t & 2047u;        // 32B chunk within the 64KB plane
    unsigned int cp   = (t >> 11) & 127u; // channel pair
    unsigned int b    = t >> 18;          // batch 0..15

    unsigned int v = cp << 1;             // even channel index
    unsigned int h = idx8 >> 4;           // 16 chunks per W=128 row

    unsigned int base = (b * C_DIM + v) * HW + (idx8 << 3);

    // Two independent 32B/lane loads (even + odd channel of the pair).
    f8 xe = ld8(feats + base);
    f8 xo = ld8(feats + base + HW);

    // 2x2 rotation block; warp-uniform per h, L2-resident.
    const float* __restrict__ Rblk =
        R + (size_t)h * (C_DIM * C_DIM) + (size_t)v * C_DIM + v;
    float c00 = __ldg(Rblk + 0);
    float c01 = __ldg(Rblk + 1);
    float c10 = __ldg(Rblk + C_DIM);
    float c11 = __ldg(Rblk + C_DIM + 1);

    f8 ye, yo;
#pragma unroll
    for (int i = 0; i < 8; i++) {
        ye.v[i] = fmaf(c00, xe.v[i], c01 * xo.v[i]);
        yo.v[i] = fmaf(c10, xe.v[i], c11 * xo.v[i]);
    }

    st8_cs(out + base,      ye);
    st8_cs(out + base + HW, yo);
}

extern "C" void kernel_launch(void* const* d_in, const int* in_sizes, int n_in,
                              void* d_out, int out_size)
{
    const float* feats = (const float*)d_in[0];
    const float* R     = (const float*)d_in[1];
    if (n_in >= 2 && in_sizes[0] < in_sizes[1]) {  // feats is the bigger input
        const float* tmp = feats; feats = R; R = tmp;
    }
    float* out = (float*)d_out;

    // 4,194,304 threads / 256 = 16,384 blocks
    rope_pair_kernel<<<16384u, 256u>>>(feats, R, out);
}